// round 2
// baseline (speedup 1.0000x reference)
#include <cuda_runtime.h>
#include <stdint.h>

#define BB 32
#define AA 65536
#define CC 21
#define NANCH (BB*AA)
#define MAIN_BLOCKS (NANCH/256)
#define SUBS 16
#define PERTH (AA/(SUBS*256))   // 16 elements per thread in pass kernels

// ---------------- scratch (device globals; no allocation allowed) ----------
__device__ float        g_neg[NANCH];       // neg_cand per anchor (8 MB, L2-resident)
__device__ unsigned int g_hist[BB*256];     // per-row 256-bin histogram (reused per level)
__device__ int          g_numpos[BB];
__device__ unsigned int g_prefix[BB];       // accumulated high bits of k-th largest value
__device__ long long    g_krem[BB];         // remaining count to select (ties at threshold)
__device__ double       g_sumgt[BB];        // per-row sum of values strictly above threshold
__device__ double       g_locsum;           // global smooth-L1 sum over positives
__device__ double       g_posce;            // global CE sum over positives

// ---------------- helpers ---------------------------------------------------
__device__ __forceinline__ double blockReduceD(double x, double* sred) {
    int lane = threadIdx.x & 31, wid = threadIdx.x >> 5;
#pragma unroll
    for (int o = 16; o; o >>= 1) x += __shfl_down_sync(0xffffffffu, x, o);
    if (lane == 0) sred[wid] = x;
    __syncthreads();
    double r = (lane < 8 && wid == 0) ? sred[lane] : 0.0;
    if (wid == 0) {
#pragma unroll
        for (int o = 4; o; o >>= 1) r += __shfl_down_sync(0xffffffffu, r, o);
    }
    return r;  // valid on thread 0
}

// ---------------- kernels ----------------------------------------------------
__global__ void init_k() {
    int t = threadIdx.x;
    for (int i = t; i < BB*256; i += 256) g_hist[i] = 0u;
    if (t < BB) { g_numpos[t] = 0; g_prefix[t] = 0u; g_krem[t] = 0; g_sumgt[t] = 0.0; }
    if (t == 0) { g_locsum = 0.0; g_posce = 0.0; }
}

__global__ void __launch_bounds__(256) main_k(const float* __restrict__ locp,
                                              const float* __restrict__ loct,
                                              const float* __restrict__ cls,
                                              const int* __restrict__ tgt) {
    __shared__ float        scls[256*CC];   // 21504 B
    __shared__ unsigned int shist[256];
    __shared__ double       sred[8];

    const int tid    = threadIdx.x;
    const int anchor = blockIdx.x * 256 + tid;
    const int row    = anchor >> 16;

    // stage cls tile (coalesced float4)
    {
        const float4* src = reinterpret_cast<const float4*>(cls) + (size_t)blockIdx.x * (256*CC/4);
        float4*       dst = reinterpret_cast<float4*>(scls);
#pragma unroll
        for (int i = 0; i < 6; i++) {
            int idx = tid + i * 256;
            if (idx < 256*CC/4) dst[idx] = src[idx];
        }
    }
    shist[tid] = 0u;
    __syncthreads();

    int t = tgt[anchor];
    bool pos = (t > 0);

    // logsumexp over 21 classes from shared (stride-21 is bank-conflict-free)
    float v[CC];
#pragma unroll
    for (int c = 0; c < CC; c++) v[c] = scls[tid*CC + c];
    float m = v[0];
#pragma unroll
    for (int c = 1; c < CC; c++) m = fmaxf(m, v[c]);
    float s = 0.f;
#pragma unroll
    for (int c = 0; c < CC; c++) s += __expf(v[c] - m);

    int tc = t; tc = tc < 0 ? 0 : (tc > CC-1 ? CC-1 : tc);
    float picked = scls[tid*CC + tc];
    float ce   = (t == -1) ? 0.f : (m + __logf(s) - picked);
    float negc = pos ? 0.f : ce;
    g_neg[anchor] = negc;

    // smooth-L1 on positive anchors (float4 aligned)
    float lsum = 0.f;
    if (pos) {
        float4 p = reinterpret_cast<const float4*>(locp)[anchor];
        float4 q = reinterpret_cast<const float4*>(loct)[anchor];
        float d0 = p.x-q.x, d1 = p.y-q.y, d2 = p.z-q.z, d3 = p.w-q.w;
        float a0 = fabsf(d0), a1 = fabsf(d1), a2 = fabsf(d2), a3 = fabsf(d3);
        lsum = (a0 < 1.f ? 0.5f*d0*d0 : a0-0.5f)
             + (a1 < 1.f ? 0.5f*d1*d1 : a1-0.5f)
             + (a2 < 1.f ? 0.5f*d2*d2 : a2-0.5f)
             + (a3 < 1.f ? 0.5f*d3*d3 : a3-0.5f);
    }

    // level-0 histogram of float bits (warp-aggregated; bin 0 is hot)
    {
        unsigned bits = __float_as_uint(negc);
        unsigned bin  = bits >> 24;
        unsigned mk   = __match_any_sync(0xffffffffu, bin);
        if ((tid & 31) == (__ffs(mk) - 1))
            atomicAdd(&shist[bin], (unsigned)__popc(mk));
    }

    int npos = __syncthreads_count(pos ? 1 : 0);   // barrier also orders shist

    double bl = blockReduceD((double)lsum, sred);
    __syncthreads();
    double bp = blockReduceD(pos ? (double)ce : 0.0, sred);

    if (tid == 0) {
        atomicAdd(&g_locsum, bl);
        atomicAdd(&g_posce,  bp);
        atomicAdd(&g_numpos[row], npos);
    }
    if (shist[tid]) atomicAdd(&g_hist[row*256 + tid], shist[tid]);
}

// pick digit for this radix level; zero histogram for reuse
__global__ void __launch_bounds__(256) scan_k(int level) {
    const int row = blockIdx.x;
    __shared__ unsigned int cnt[256];
    int tid = threadIdx.x;
    cnt[tid] = g_hist[row*256 + tid];
    __syncthreads();
    if (tid == 0) {
        long long krem;
        if (level == 0) {
            long long k = 3LL * (long long)g_numpos[row];
            if (k < 1) k = 1;
            if (k > AA-1) k = AA-1;
            krem = k;
        } else {
            krem = g_krem[row];
        }
        long long above = 0;
        int d = 255;
        for (; d > 0; --d) {
            if (above + (long long)cnt[d] >= krem) break;
            above += (long long)cnt[d];
        }
        g_krem[row]   = krem - above;
        g_prefix[row] = (g_prefix[row] << 8) | (unsigned)d;
    }
    __syncthreads();
    g_hist[row*256 + tid] = 0u;
}

// histogram of next 8 bits among values matching current prefix
__global__ void __launch_bounds__(256) hist_k(int shift) {
    const int row = blockIdx.x >> 4;
    const int sub = blockIdx.x & 15;
    __shared__ unsigned int shist[256];
    int tid = threadIdx.x;
    shist[tid] = 0u;
    __syncthreads();

    const unsigned pfx  = g_prefix[row];
    const float*   base = g_neg + (size_t)row*AA + sub*(AA/SUBS);
#pragma unroll
    for (int i = 0; i < PERTH; i++) {
        unsigned bits = __float_as_uint(base[tid + i*256]);
        if ((bits >> (shift + 8)) == pfx) {
            unsigned bin = (bits >> shift) & 255u;
            unsigned act = __activemask();
            unsigned mk  = __match_any_sync(act, bin);
            if ((unsigned)(tid & 31) == (unsigned)(__ffs(mk) - 1))
                atomicAdd(&shist[bin], (unsigned)__popc(mk));
        }
    }
    __syncthreads();
    if (shist[tid]) atomicAdd(&g_hist[row*256 + tid], shist[tid]);
}

// sum of values strictly above threshold, per row
__global__ void __launch_bounds__(256) sumgt_k() {
    const int row = blockIdx.x >> 4;
    const int sub = blockIdx.x & 15;
    __shared__ double sred[8];
    const unsigned tb   = g_prefix[row];
    const float*   base = g_neg + (size_t)row*AA + sub*(AA/SUBS);
    int tid = threadIdx.x;
    double s = 0.0;
#pragma unroll
    for (int i = 0; i < PERTH; i++) {
        float v = base[tid + i*256];
        if (__float_as_uint(v) > tb) s += (double)v;
    }
    double bs = blockReduceD(s, sred);
    if (tid == 0) atomicAdd(&g_sumgt[row], bs);
}

__global__ void comb_k(float* out) {
    double tp = 0.0;
    for (int b = 0; b < BB; b++) tp += (double)g_numpos[b];
    double negsum = 0.0;
    for (int b = 0; b < BB; b++) {
        float tval = __uint_as_float(g_prefix[b]);
        negsum += g_sumgt[b] + (double)g_krem[b] * (double)tval;
    }
    double loc  = g_locsum / tp;
    double clsl = (g_posce + negsum) / tp;
    out[0] = (float)(20.0 * loc);
    out[1] = (float)clsl;
}

// ---------------- launch -----------------------------------------------------
extern "C" void kernel_launch(void* const* d_in, const int* in_sizes, int n_in,
                              void* d_out, int out_size) {
    const float* locp = (const float*)d_in[0];
    const float* loct = (const float*)d_in[1];
    const float* cls  = (const float*)d_in[2];
    const int*   tgt  = (const int*)d_in[3];
    float* out = (float*)d_out;

    init_k<<<1, 256>>>();
    main_k<<<MAIN_BLOCKS, 256>>>(locp, loct, cls, tgt);
    scan_k<<<BB, 256>>>(0);
    hist_k<<<BB*SUBS, 256>>>(16);
    scan_k<<<BB, 256>>>(1);
    hist_k<<<BB*SUBS, 256>>>(8);
    scan_k<<<BB, 256>>>(2);
    hist_k<<<BB*SUBS, 256>>>(0);
    scan_k<<<BB, 256>>>(3);
    sumgt_k<<<BB*SUBS, 256>>>();
    comb_k<<<1, 1>>>(out);
}